// round 3
// baseline (speedup 1.0000x reference)
#include <cuda_runtime.h>
#include <cuda_bf16.h>

// LearnableQuantization: out = gumbel-softmax over 17-bin log-sigmoid CDF grid.
// Softmax denominator of pi cancels; z_g ∝ sqrt(num_g) * (-log U_g)^(-1/2)
// (exact collapse of softmax((log pi + gumbel)/TEMP), TEMP=2).
//
// PRNG: jax threefry2x32, PARTITIONABLE mode (modern jax default):
//   word i = y0 ^ y1 of threefry2x32(key=(0,1), x0=hi32(i)=0, x1=lo32(i)).
// Uniform: f = bitcast((bits>>9)|0x3f800000)-1; u = max(tiny, f).
// gumbel u_g = -log(-log U); exp(u_g/2) = rsqrt(-log U).

#define N_ELEMS   3145728            // 16*3*1024*8*8
#define RC_INV    (1.0f / 49152.0f)

__device__ float g_mean_accum[64];

__device__ __forceinline__ unsigned tf_rotl(unsigned x, int r) {
    return __funnelshift_l(x, x, r);
}

// threefry2x32-20, key (0,1), block (0, i); returns y0 ^ y1.
__device__ __forceinline__ unsigned tf_bits(unsigned i) {
    const unsigned ks1 = 1u, ks2 = 0x1BD11BDBu; // ks0=0, ks2=0x1BD11BDA^0^1
    unsigned x0 = 0u;            // c0 + ks0
    unsigned x1 = i + ks1;       // c1 + ks1
#define TF_RND(r) { x0 += x1; x1 = tf_rotl(x1, (r)); x1 ^= x0; }
    TF_RND(13) TF_RND(15) TF_RND(26) TF_RND(6)
    x0 += ks1; x1 += ks2 + 1u;
    TF_RND(17) TF_RND(29) TF_RND(16) TF_RND(24)
    x0 += ks2; x1 += 0u + 2u;
    TF_RND(13) TF_RND(15) TF_RND(26) TF_RND(6)
    x0 += 0u;  x1 += ks1 + 3u;
    TF_RND(17) TF_RND(29) TF_RND(16) TF_RND(24)
    x0 += ks1; x1 += ks2 + 4u;
    TF_RND(13) TF_RND(15) TF_RND(26) TF_RND(6)
    x0 += ks2; x1 += 0u + 5u;
#undef TF_RND
    return x0 ^ x1;
}

// exp(gumbel/2) = (-log U)^(-1/2). Fast __logf is safe: where its absolute
// error (~2^-21) is non-negligible relative to -log U, U ~ 1 and that bin's
// weight dominates the softmax either way. Clamp keeps rsqrt arg positive.
__device__ __forceinline__ float gumbel_halfexp(unsigned bits) {
    float f = __uint_as_float((bits >> 9) | 0x3f800000u) - 1.0f;
    float u = fmaxf(f, 1.17549435e-38f);
    float t = fmaxf(-__logf(u), 1e-37f);
    return rsqrtf(t);
}

// softplus(s) = max(s,0) + log1p(exp(-|s|)); fast intrinsics fine
// (abs error ~5e-7 against the +0.2 floor in num).
__device__ __forceinline__ float softplus_f(float s) {
    return fmaxf(s, 0.0f) + __logf(1.0f + __expf(-fabsf(s)));
}

__global__ void lq_zero_kernel() {
    g_mean_accum[threadIdx.x] = 0.0f;   // <<<1,64>>>
}

__global__ void __launch_bounds__(256) lq_main_kernel(
    const float* __restrict__ x,
    const float* __restrict__ alpha,
    const float* __restrict__ dev,
    float* __restrict__ out)
{
    __shared__ float s_alpha[64], s_invd[64], s_inva[64], s_macc[64];
    int tid = threadIdx.x;
    if (tid < 64) {
        float a = alpha[tid];
        float d = dev[tid];
        s_alpha[tid] = a;
        s_inva[tid]  = 1.0f / a;
        s_invd[tid]  = 1.0f / d;
        s_macc[tid]  = 0.0f;
    }
    __syncthreads();

    int e  = blockIdx.x * 256 + tid;     // grid sized exactly: no bounds check
    int rc = e & 63;
    float a    = s_alpha[rc];
    float invd = s_invd[rc];
    float xv   = x[e];

    // mean contribution: |x / alpha| (reciprocal-mul: rel err ~1e-7, fine)
    atomicAdd(&s_macc[rc], fabsf(xv * s_inva[rc]));

    // grid_g = (g-8.5)*alpha for g=0..15; grid_16 = 8.5*alpha (last base +=1)
    float sp_prev = softplus_f((xv - __fmul_rn(-8.5f, a)) * invd);
    float sum = 0.0f, ws = 0.0f;
    unsigned base = (unsigned)e * 16u;

#pragma unroll 4
    for (int g = 0; g < 16; ++g) {
        float bn  = (g == 15) ? 8.5f : ((float)(g + 1) - 8.5f);
        float sp  = softplus_f((xv - __fmul_rn(bn, a)) * invd);
        // num = cdf[g+1]-cdf[g]+0.2 = sp_g - sp_{g+1} + 0.2 (> 0.199 always)
        float num = sp_prev - sp + 0.2f;
        sp_prev = sp;

        float w   = sqrtf(num) * gumbel_halfexp(tf_bits(base + (unsigned)g));
        float grd = __fmul_rn((float)g - 8.5f, a);
        sum += w;
        ws   = __fmaf_rn(w, grd, ws);
    }
    out[e] = ws / sum;

    __syncthreads();
    if (tid < 64) atomicAdd(&g_mean_accum[tid], s_macc[tid]);
}

__global__ void lq_final_kernel(float* __restrict__ out, int out_size) {
    int i = threadIdx.x;   // <<<1,64>>>
    if (out_size > N_ELEMS + i)
        out[N_ELEMS + i] = g_mean_accum[i] * RC_INV;
    if (i == 0 && out_size > N_ELEMS + 64)
        out[N_ELEMS + 64] = 0.0f;   // nzeros
}

extern "C" void kernel_launch(void* const* d_in, const int* in_sizes, int n_in,
                              void* d_out, int out_size) {
    const float* x     = (const float*)d_in[0];
    const float* alpha = (const float*)d_in[1];
    const float* dev   = (const float*)d_in[2];
    float* out = (float*)d_out;

    lq_zero_kernel<<<1, 64>>>();
    lq_main_kernel<<<N_ELEMS / 256, 256>>>(x, alpha, dev, out);
    lq_final_kernel<<<1, 64>>>(out, out_size);
}